// round 5
// baseline (speedup 1.0000x reference)
#include <cuda_runtime.h>
#include <math.h>

// Problem constants
#define BTOT    262144
#define NBR     21
#define NDIM    16
#define FEATD   336      // 21*16
#define H1D     256
#define H2D     128
#define NATT    20
#define NAMT    30
#define NNODES  100000

// Tiling
#define MT       64      // samples per CTA
#define NTHREADS 256
#define HSTR     68      // padded stride for h1T/h2T (bank-conflict-free stores, 16B aligned)

struct SM {
    float featT[FEATD][MT];   // K-major feature tile  (336*64)
    float h1T[H1D][HSTR];     // hidden1, K-major      (256*68)
    float h2T[H2D][HSTR];     // hidden2, K-major      (128*68)
    float wbuf[2][2048];      // double-buffered weight chunks / small-layer weights
    float logits[MT][33];     // padded (33) logits per sample
    float bbuf[512];          // [0..255] bias, [256..511] last w1-row for amt path
    float mv[MT];             // masked_value per sample
    int   cols[MT * NBR];     // gathered edge column ids
};

// ---------------------------------------------------------------------------
// JAX PARTITIONABLE threefry2x32 random bits (default since jax 0.4.36).
// For a (B,30) fp32 draw with key=jax.random.key(1) -> key data (0,1):
//   counter for flat index i is the 64-bit iota split into (hi32, lo32);
//   here size < 2^32 so hi = 0, lo = i.
//   32-bit output = lane0 ^ lane1   (prng.py: bits1 ^ bits2)
// Then jax uniform bit-trick + gumbel = -log(-log(u)).
// ---------------------------------------------------------------------------
__device__ __forceinline__ float gumbel_at(unsigned t) {
    const unsigned ks0 = 0u, ks1 = 1u, ks2 = 0x1BD11BDBu;  // 0^1^0x1BD11BDA
    unsigned ksv[3] = {ks0, ks1, ks2};
    unsigned x0 = 0u + ks0;      // counter hi word = 0
    unsigned x1 = t  + ks1;      // counter lo word = flat index
    const int R0[4] = {13, 15, 26, 6};
    const int R1[4] = {17, 29, 16, 24};
#pragma unroll
    for (int i = 0; i < 5; i++) {
#pragma unroll
        for (int j = 0; j < 4; j++) {
            int r = (i & 1) ? R1[j] : R0[j];
            x0 += x1;
            x1 = (x1 << r) | (x1 >> (32 - r));
            x1 ^= x0;
        }
        x0 += ksv[(i + 1) % 3];
        x1 += ksv[(i + 2) % 3] + (unsigned)(i + 1);
    }
    unsigned bits = x0 ^ x1;
    // jax uniform: bitcast((bits>>9)|0x3f800000)-1 -> [0,1), then max(tiny, .)
    float u = __uint_as_float((bits >> 9) | 0x3f800000u) - 1.0f;
    u = fmaxf(u, 1.17549435e-38f);
    return -logf(-logf(u));
}

// ---------------------------------------------------------------------------
// Fused tiled GEMM:  dstT[n][m] = relu( sum_k srcT[k][m]*Wg[k][n] + bias[n]
//                                       (+ mv[m]*wlast[n]) )
// 256 threads: tx = t&15 (N), ty = t>>4 (M). Thread tile 4(M) x (N/16).
// Weights streamed from global (L2-resident) in 8-row chunks, double buffered.
// ---------------------------------------------------------------------------
template<int K, int N, int SSTR>
__device__ __forceinline__ void gemm_block(
    const float* __restrict__ srcT, float* __restrict__ dstT, int dstr,
    const float* __restrict__ Wg, SM& s,
    const float* __restrict__ bias_sm,
    const float* __restrict__ mvp, const float* __restrict__ wlast_sm,
    int t)
{
    const int tx = t & 15;
    const int ty = t >> 4;
    constexpr int NGR = N / 64;        // groups of 4 in N per thread
    constexpr int NKB = K / 8;

    // preload chunk 0
    {
        int r  = t >> 5;
        int cb = (t & 31) * 4;
        const float* src = Wg + r * N;
#pragma unroll
        for (int u = 0; u < N / 128; u++)
            *reinterpret_cast<float4*>(&s.wbuf[0][r * N + cb + u * 128]) =
                *reinterpret_cast<const float4*>(&src[cb + u * 128]);
    }
    __syncthreads();   // also orders caller's srcT / bias stores

    float c[4][NGR * 4];
#pragma unroll
    for (int mi = 0; mi < 4; mi++)
#pragma unroll
        for (int g = 0; g < NGR; g++)
#pragma unroll
            for (int v = 0; v < 4; v++)
                c[mi][g * 4 + v] = bias_sm[tx * 4 + 64 * g + v];

    for (int kb = 0; kb < NKB; kb++) {
        const float* cur = s.wbuf[kb & 1];
        float* nxt = s.wbuf[(kb & 1) ^ 1];
        if (kb + 1 < NKB) {
            int r  = t >> 5;
            int cb = (t & 31) * 4;
            const float* src = Wg + ((kb + 1) * 8 + r) * N;
#pragma unroll
            for (int u = 0; u < N / 128; u++)
                *reinterpret_cast<float4*>(&nxt[r * N + cb + u * 128]) =
                    *reinterpret_cast<const float4*>(&src[cb + u * 128]);
        }
#pragma unroll
        for (int kc = 0; kc < 8; kc++) {
            const float* arow = srcT + (kb * 8 + kc) * SSTR;
            float4 a4 = *reinterpret_cast<const float4*>(&arow[ty * 4]);
            float a[4] = {a4.x, a4.y, a4.z, a4.w};
            float b[NGR * 4];
#pragma unroll
            for (int g = 0; g < NGR; g++) {
                float4 b4 = *reinterpret_cast<const float4*>(&cur[kc * N + tx * 4 + 64 * g]);
                b[g * 4 + 0] = b4.x; b[g * 4 + 1] = b4.y;
                b[g * 4 + 2] = b4.z; b[g * 4 + 3] = b4.w;
            }
#pragma unroll
            for (int mi = 0; mi < 4; mi++)
#pragma unroll
                for (int n = 0; n < NGR * 4; n++)
                    c[mi][n] = fmaf(a[mi], b[n], c[mi][n]);
        }
        __syncthreads();
    }

    if (mvp != nullptr) {   // extra K-term: concat(feature, masked_value)
        float a[4];
#pragma unroll
        for (int mi = 0; mi < 4; mi++) a[mi] = mvp[ty * 4 + mi];
#pragma unroll
        for (int g = 0; g < NGR; g++)
#pragma unroll
            for (int v = 0; v < 4; v++) {
                float w = wlast_sm[tx * 4 + 64 * g + v];
#pragma unroll
                for (int mi = 0; mi < 4; mi++)
                    c[mi][g * 4 + v] = fmaf(a[mi], w, c[mi][g * 4 + v]);
            }
    }

    // relu + store K-major
#pragma unroll
    for (int g = 0; g < NGR; g++)
#pragma unroll
        for (int v = 0; v < 4; v++) {
            int n = tx * 4 + 64 * g + v;
#pragma unroll
            for (int mi = 0; mi < 4; mi++)
                dstT[n * dstr + ty * 4 + mi] = fmaxf(c[mi][g * 4 + v], 0.0f);
        }
}

__global__ __launch_bounds__(NTHREADS, 1)
void att_amt_policy_kernel(
    const float* __restrict__ x,
    const int* __restrict__ edge_col,            // edge_index row 1 (int32)
    const float* __restrict__ actual_amount,
    const int* __restrict__ real_act,            // int32
    const float* __restrict__ att_w1, const float* __restrict__ att_b1,
    const float* __restrict__ att_w2, const float* __restrict__ att_b2,
    const float* __restrict__ att_w3, const float* __restrict__ att_b3,
    const float* __restrict__ amt_w1, const float* __restrict__ amt_b1,
    const float* __restrict__ amt_w2, const float* __restrict__ amt_b2,
    const float* __restrict__ amt_w3, const float* __restrict__ amt_b3,
    float* __restrict__ out)
{
    extern __shared__ char smraw[];
    SM& s = *reinterpret_cast<SM*>(smraw);
    const int t    = threadIdx.x;
    const int base = blockIdx.x * MT;
    float* wflat = &s.wbuf[0][0];

    // ---------------- phase 0: cols (coalesced), masked_value ----------------
    for (int p = t; p < MT * NBR; p += NTHREADS) {
        int c = edge_col[(long long)base * NBR + p];
        c = min(max(c, 0), NNODES - 1);          // defensive clamp
        s.cols[p] = c;
    }
    if (t < MT) {
        int i = base + t;
        int r = real_act[i];
        r = min(max(r, 0), NBR - 1);             // defensive clamp
        const float* aarow = actual_amount + (long long)i * NBR * 2;
        float p0  = aarow[r * 2 + 0];
        float p1  = aarow[r * 2 + 1];
        float a00 = aarow[0];
        s.mv[t] = (a00 > 0.0f) ? p0 : -p1;
    }
    __syncthreads();

    // ---------------- phase 1: gather features (s-major: conflict-free STS) --
    for (int q = t; q < MT * NBR; q += NTHREADS) {
        int ss = q & (MT - 1);
        int j  = q >> 6;                       // MT == 64
        int node = s.cols[ss * NBR + j];
        const float4* xr = reinterpret_cast<const float4*>(x + (long long)node * NDIM);
#pragma unroll
        for (int v = 0; v < 4; v++) {
            float4 w = xr[v];
            s.featT[j * NDIM + v * 4 + 0][ss] = w.x;
            s.featT[j * NDIM + v * 4 + 1][ss] = w.y;
            s.featT[j * NDIM + v * 4 + 2][ss] = w.z;
            s.featT[j * NDIM + v * 4 + 3][ss] = w.w;
        }
    }
    // (gemm_block's first __syncthreads orders these stores)

    // ============================ ATT branch ================================
    for (int p = t; p < H1D; p += NTHREADS) s.bbuf[p] = att_b1[p];
    gemm_block<FEATD, H1D, MT>(&s.featT[0][0], &s.h1T[0][0], HSTR,
                               att_w1, s, s.bbuf, nullptr, nullptr, t);

    for (int p = t; p < H2D; p += NTHREADS) s.bbuf[p] = att_b2[p];
    gemm_block<H1D, H2D, HSTR>(&s.h1T[0][0], &s.h2T[0][0], HSTR,
                               att_w2, s, s.bbuf, nullptr, nullptr, t);

    // GEMM3 att: 64x20, K=128
    for (int p = t; p < H2D * NATT; p += NTHREADS) wflat[p] = att_w3[p];
    __syncthreads();
    {
        int ssp = t & 63;
        int g   = t >> 6;                      // 4 groups x 5 outputs
        float acc[5];
#pragma unroll
        for (int j = 0; j < 5; j++) acc[j] = att_b3[g * 5 + j];
        for (int k = 0; k < H2D; k++) {
            float a = s.h2T[k][ssp];
#pragma unroll
            for (int j = 0; j < 5; j++)
                acc[j] = fmaf(a, wflat[k * NATT + g * 5 + j], acc[j]);
        }
#pragma unroll
        for (int j = 0; j < 5; j++) s.logits[ssp][g * 5 + j] = acc[j];
    }
    __syncthreads();

    // att softmax + store
    if (t < MT) {
        int i = base + t;
        float l[NATT];
        float mx = -1e30f;
#pragma unroll
        for (int n = 0; n < NATT; n++) { l[n] = s.logits[t][n]; mx = fmaxf(mx, l[n]); }
        float sum = 0.f;
#pragma unroll
        for (int n = 0; n < NATT; n++) { l[n] = expf(l[n] - mx); sum += l[n]; }
        float inv = 1.0f / sum;
        float* od = out + (size_t)BTOT + (size_t)i * NATT;
#pragma unroll
        for (int n = 0; n < NATT; n++) od[n] = l[n] * inv;
    }
    __syncthreads();

    // ============================ AMT branch ================================
    for (int p = t; p < H1D; p += NTHREADS) {
        s.bbuf[p]       = amt_b1[p];
        s.bbuf[256 + p] = amt_w1[(size_t)FEATD * H1D + p];  // row 336 (masked_value)
    }
    gemm_block<FEATD, H1D, MT>(&s.featT[0][0], &s.h1T[0][0], HSTR,
                               amt_w1, s, s.bbuf, s.mv, s.bbuf + 256, t);

    for (int p = t; p < H2D; p += NTHREADS) s.bbuf[p] = amt_b2[p];
    gemm_block<H1D, H2D, HSTR>(&s.h1T[0][0], &s.h2T[0][0], HSTR,
                               amt_w2, s, s.bbuf, nullptr, nullptr, t);

    // GEMM3 amt: 64x30, K=128
    for (int p = t; p < H2D * NAMT; p += NTHREADS) wflat[p] = amt_w3[p];
    __syncthreads();
    {
        int ssp = t & 63;
        int g   = t >> 6;                      // groups of 8 (last has 6)
        int n0  = g * 8;
        float acc[8];
#pragma unroll
        for (int j = 0; j < 8; j++)
            acc[j] = (n0 + j < NAMT) ? amt_b3[n0 + j] : 0.f;
        for (int k = 0; k < H2D; k++) {
            float a = s.h2T[k][ssp];
#pragma unroll
            for (int j = 0; j < 8; j++)
                if (n0 + j < NAMT)
                    acc[j] = fmaf(a, wflat[k * NAMT + n0 + j], acc[j]);
        }
#pragma unroll
        for (int j = 0; j < 8; j++)
            if (n0 + j < NAMT) s.logits[ssp][n0 + j] = acc[j];
    }
    __syncthreads();

    // ------------- amt softmax -> mask -> softmax -> gumbel argmax ----------
    if (t < MT) {
        int i = base + t;
        float l[NAMT];
        float mx = -1e30f;
#pragma unroll
        for (int n = 0; n < NAMT; n++) { l[n] = s.logits[t][n]; mx = fmaxf(mx, l[n]); }
        float sum = 0.f;
#pragma unroll
        for (int n = 0; n < NAMT; n++) { l[n] = expf(l[n] - mx); sum += l[n]; }
        float inv = 1.0f / sum;
#pragma unroll
        for (int n = 0; n < NAMT; n++) l[n] *= inv;           // amt_probs

        // bucket threshold: clamp(ceil((mv/0.1)/2), 1, 30)
        float mvv = s.mv[t];
        float a1 = mvv / 0.1f;
        a1 = a1 / 2.0f;
        float cf = ceilf(a1);
        cf = fminf(fmaxf(cf, 1.0f), 30.0f);
        int temp = (int)cf;

        // second (masked) softmax over first `temp` buckets
        float mx2 = -1e30f;
        for (int n = 0; n < temp; n++) mx2 = fmaxf(mx2, l[n]);
        float sum2 = 0.f;
#pragma unroll
        for (int n = 0; n < NAMT; n++) {
            float e = (n < temp) ? expf(l[n] - mx2) : 0.f;
            l[n] = e;
            sum2 += e;
        }
        float inv2 = 1.0f / sum2;

        float* od = out + (size_t)BTOT * (1 + NATT) + (size_t)i * NAMT;
        int best = 0;
        float bestsc = -1e30f;
        unsigned gbase = (unsigned)i * (unsigned)NAMT;
#pragma unroll
        for (int n = 0; n < NAMT; n++) {
            float a = l[n] * inv2;            // exact 0 for masked buckets
            od[n] = a;
            float sc = logf(a + 1e-20f) + gumbel_at(gbase + n);
            if (sc > bestsc) { bestsc = sc; best = n; }
        }
        out[i] = (float)best;                  // cnt
    }
}

extern "C" void kernel_launch(void* const* d_in, const int* in_sizes, int n_in,
                              void* d_out, int out_size) {
    const float* x  = (const float*)d_in[0];
    const int*   ei = (const int*)d_in[1];      // int32 (jax x64 disabled)
    const float* aa = (const float*)d_in[2];
    const int*   ra = (const int*)d_in[3];      // int32
    const float *aw1 = (const float*)d_in[4],  *ab1 = (const float*)d_in[5];
    const float *aw2 = (const float*)d_in[6],  *ab2 = (const float*)d_in[7];
    const float *aw3 = (const float*)d_in[8],  *ab3 = (const float*)d_in[9];
    const float *mw1 = (const float*)d_in[10], *mb1 = (const float*)d_in[11];
    const float *mw2 = (const float*)d_in[12], *mb2 = (const float*)d_in[13];
    const float *mw3 = (const float*)d_in[14], *mb3 = (const float*)d_in[15];
    float* out = (float*)d_out;

    cudaFuncSetAttribute(att_amt_policy_kernel,
                         cudaFuncAttributeMaxDynamicSharedMemorySize,
                         (int)sizeof(SM));
    const int* edge_col = ei + (long long)BTOT * NBR;  // edge_index[1]
    att_amt_policy_kernel<<<BTOT / MT, NTHREADS, sizeof(SM)>>>(
        x, edge_col, aa, ra,
        aw1, ab1, aw2, ab2, aw3, ab3,
        mw1, mb1, mw2, mb2, mw3, mb3,
        out);
}

// round 6
// speedup vs baseline: 1.0701x; 1.0701x over previous
#include <cuda_runtime.h>
#include <math.h>

// Problem constants
#define BTOT    262144
#define NBR     21
#define NDIM    16
#define FEATD   336      // 21*16
#define H1D     256
#define H2D     128
#define NATT    20
#define NAMT    30
#define NNODES  100000

// Tiling
#define MT       64      // samples per CTA
#define NTHREADS 256
#define HSTR     68      // padded stride for h1T/h2T

struct SM {
    float featT[FEATD][MT];   // K-major feature tile  (336*64)
    float h1T[H1D][HSTR];     // hidden1, K-major      (256*68)
    float h2T[H2D][HSTR];     // hidden2, K-major      (128*68)
    float wbuf[2][2048];      // double-buffered weight chunks / small-layer weights
    float logits[MT][33];     // padded (33) logits per sample
    float bbuf[512];          // [0..255] bias, [256..511] last w1-row for amt path
    float mv[MT];             // masked_value per sample
    int   cols[MT * NBR];     // gathered edge column ids
};

// ---------------------------------------------------------------------------
// packed fp32x2 helpers (sm_100a): bit-identical per-lane IEEE fp32 FMA
// ---------------------------------------------------------------------------
union F2 { unsigned long long u; float2 f; };

__device__ __forceinline__ void fma2(unsigned long long& c,
                                     unsigned long long a,
                                     unsigned long long b) {
    asm("fma.rn.f32x2 %0, %1, %2, %0;" : "+l"(c) : "l"(a), "l"(b));
}
__device__ __forceinline__ unsigned long long pack2(float lo, float hi) {
    unsigned long long r;
    asm("mov.b64 %0, {%1, %2};" : "=l"(r) : "f"(lo), "f"(hi));
    return r;
}

// ---------------------------------------------------------------------------
// JAX PARTITIONABLE threefry2x32 bits (default since jax 0.4.36):
// counter=(0, flat_idx), key=(0,1), output = lane0 ^ lane1. Then the jax
// uniform bit-trick and gumbel = -log(-log(u)).
// ---------------------------------------------------------------------------
__device__ __forceinline__ float gumbel_at(unsigned t) {
    const unsigned ks0 = 0u, ks1 = 1u, ks2 = 0x1BD11BDBu;
    unsigned ksv[3] = {ks0, ks1, ks2};
    unsigned x0 = 0u + ks0;
    unsigned x1 = t  + ks1;
    const int R0[4] = {13, 15, 26, 6};
    const int R1[4] = {17, 29, 16, 24};
#pragma unroll
    for (int i = 0; i < 5; i++) {
#pragma unroll
        for (int j = 0; j < 4; j++) {
            int r = (i & 1) ? R1[j] : R0[j];
            x0 += x1;
            x1 = (x1 << r) | (x1 >> (32 - r));
            x1 ^= x0;
        }
        x0 += ksv[(i + 1) % 3];
        x1 += ksv[(i + 2) % 3] + (unsigned)(i + 1);
    }
    unsigned bits = x0 ^ x1;
    float u = __uint_as_float((bits >> 9) | 0x3f800000u) - 1.0f;
    u = fmaxf(u, 1.17549435e-38f);
    return -logf(-logf(u));
}

// ---------------------------------------------------------------------------
// Fused tiled GEMM (f32x2 inner loop):
//   dstT[n][m] = relu( sum_k srcT[k][m]*Wg[k][n] + bias[n] (+ mv[m]*wlast[n]) )
// 256 threads: tx=t&15 (N), ty=t>>4 (M). Thread tile 4(M) x N/16, packed as
// N-pairs. Weights streamed from L2 in 8-row chunks, double buffered.
// Accumulation order per element identical to the scalar version.
// ---------------------------------------------------------------------------
template<int K, int N, int SSTR>
__device__ __forceinline__ void gemm_block(
    const float* __restrict__ srcT, float* __restrict__ dstT, int dstr,
    const float* __restrict__ Wg, SM& s,
    const float* __restrict__ bias_sm,
    const float* __restrict__ mvp, const float* __restrict__ wlast_sm,
    int t)
{
    const int tx = t & 15;
    const int ty = t >> 4;
    constexpr int NGR = N / 64;        // float4 groups per thread in N
    constexpr int NP  = NGR * 2;       // f32x2 pairs per thread in N
    constexpr int NKB = K / 8;

    // preload chunk 0
    {
        int r  = t >> 5;
        int cb = (t & 31) * 4;
        const float* src = Wg + r * N;
#pragma unroll
        for (int u = 0; u < N / 128; u++)
            *reinterpret_cast<float4*>(&s.wbuf[0][r * N + cb + u * 128]) =
                *reinterpret_cast<const float4*>(&src[cb + u * 128]);
    }
    __syncthreads();   // also orders caller's srcT / bias stores

    unsigned long long c2[4][NP];
#pragma unroll
    for (int g = 0; g < NGR; g++)
#pragma unroll
        for (int h = 0; h < 2; h++) {
            int n0 = tx * 4 + 64 * g + 2 * h;
            unsigned long long bp = pack2(bias_sm[n0], bias_sm[n0 + 1]);
#pragma unroll
            for (int mi = 0; mi < 4; mi++) c2[mi][g * 2 + h] = bp;
        }

    for (int kb = 0; kb < NKB; kb++) {
        const float* cur = s.wbuf[kb & 1];
        float* nxt = s.wbuf[(kb & 1) ^ 1];
        if (kb + 1 < NKB) {
            int r  = t >> 5;
            int cb = (t & 31) * 4;
            const float* src = Wg + ((kb + 1) * 8 + r) * N;
#pragma unroll
            for (int u = 0; u < N / 128; u++)
                *reinterpret_cast<float4*>(&nxt[r * N + cb + u * 128]) =
                    *reinterpret_cast<const float4*>(&src[cb + u * 128]);
        }
#pragma unroll
        for (int kc = 0; kc < 8; kc++) {
            const float* arow = srcT + (kb * 8 + kc) * SSTR;
            float4 a4 = *reinterpret_cast<const float4*>(&arow[ty * 4]);
            unsigned long long aa[4] = {
                pack2(a4.x, a4.x), pack2(a4.y, a4.y),
                pack2(a4.z, a4.z), pack2(a4.w, a4.w)
            };
            unsigned long long bp[NP];
#pragma unroll
            for (int g = 0; g < NGR; g++) {
                ulonglong2 bv = *reinterpret_cast<const ulonglong2*>(
                    &cur[kc * N + tx * 4 + 64 * g]);
                bp[g * 2 + 0] = bv.x;
                bp[g * 2 + 1] = bv.y;
            }
#pragma unroll
            for (int mi = 0; mi < 4; mi++)
#pragma unroll
                for (int p = 0; p < NP; p++)
                    fma2(c2[mi][p], aa[mi], bp[p]);
        }
        __syncthreads();
    }

    if (mvp != nullptr) {   // extra K-term: concat(feature, masked_value)
        unsigned long long aa[4];
#pragma unroll
        for (int mi = 0; mi < 4; mi++) {
            float v = mvp[ty * 4 + mi];
            aa[mi] = pack2(v, v);
        }
#pragma unroll
        for (int g = 0; g < NGR; g++)
#pragma unroll
            for (int h = 0; h < 2; h++) {
                int n0 = tx * 4 + 64 * g + 2 * h;
                unsigned long long wl = pack2(wlast_sm[n0], wlast_sm[n0 + 1]);
#pragma unroll
                for (int mi = 0; mi < 4; mi++)
                    fma2(c2[mi][g * 2 + h], aa[mi], wl);
            }
    }

    // relu + store K-major
#pragma unroll
    for (int g = 0; g < NGR; g++)
#pragma unroll
        for (int h = 0; h < 2; h++) {
            int n0 = tx * 4 + 64 * g + 2 * h;
#pragma unroll
            for (int mi = 0; mi < 4; mi++) {
                F2 u; u.u = c2[mi][g * 2 + h];
                dstT[(n0 + 0) * dstr + ty * 4 + mi] = fmaxf(u.f.x, 0.0f);
                dstT[(n0 + 1) * dstr + ty * 4 + mi] = fmaxf(u.f.y, 0.0f);
            }
        }
}

__global__ __launch_bounds__(NTHREADS, 1)
void att_amt_policy_kernel(
    const float* __restrict__ x,
    const int* __restrict__ edge_col,            // edge_index row 1 (int32)
    const float* __restrict__ actual_amount,
    const int* __restrict__ real_act,            // int32
    const float* __restrict__ att_w1, const float* __restrict__ att_b1,
    const float* __restrict__ att_w2, const float* __restrict__ att_b2,
    const float* __restrict__ att_w3, const float* __restrict__ att_b3,
    const float* __restrict__ amt_w1, const float* __restrict__ amt_b1,
    const float* __restrict__ amt_w2, const float* __restrict__ amt_b2,
    const float* __restrict__ amt_w3, const float* __restrict__ amt_b3,
    float* __restrict__ out)
{
    extern __shared__ char smraw[];
    SM& s = *reinterpret_cast<SM*>(smraw);
    const int t    = threadIdx.x;
    const int base = blockIdx.x * MT;
    float* wflat = &s.wbuf[0][0];

    // ---------------- phase 0: cols (coalesced), masked_value ----------------
    for (int p = t; p < MT * NBR; p += NTHREADS) {
        int c = edge_col[(long long)base * NBR + p];
        c = min(max(c, 0), NNODES - 1);          // defensive clamp
        s.cols[p] = c;
    }
    if (t < MT) {
        int i = base + t;
        int r = real_act[i];
        r = min(max(r, 0), NBR - 1);             // defensive clamp
        const float* aarow = actual_amount + (long long)i * NBR * 2;
        float p0  = aarow[r * 2 + 0];
        float p1  = aarow[r * 2 + 1];
        float a00 = aarow[0];
        s.mv[t] = (a00 > 0.0f) ? p0 : -p1;
    }
    __syncthreads();

    // ---------------- phase 1: gather features ------------------------------
    for (int q = t; q < MT * NBR; q += NTHREADS) {
        int ss = q & (MT - 1);
        int j  = q >> 6;                       // MT == 64
        int node = s.cols[ss * NBR + j];
        const float4* xr = reinterpret_cast<const float4*>(x + (long long)node * NDIM);
#pragma unroll
        for (int v = 0; v < 4; v++) {
            float4 w = xr[v];
            s.featT[j * NDIM + v * 4 + 0][ss] = w.x;
            s.featT[j * NDIM + v * 4 + 1][ss] = w.y;
            s.featT[j * NDIM + v * 4 + 2][ss] = w.z;
            s.featT[j * NDIM + v * 4 + 3][ss] = w.w;
        }
    }
    // (gemm_block's first __syncthreads orders these stores)

    // ============================ ATT branch ================================
    for (int p = t; p < H1D; p += NTHREADS) s.bbuf[p] = att_b1[p];
    gemm_block<FEATD, H1D, MT>(&s.featT[0][0], &s.h1T[0][0], HSTR,
                               att_w1, s, s.bbuf, nullptr, nullptr, t);

    for (int p = t; p < H2D; p += NTHREADS) s.bbuf[p] = att_b2[p];
    gemm_block<H1D, H2D, HSTR>(&s.h1T[0][0], &s.h2T[0][0], HSTR,
                               att_w2, s, s.bbuf, nullptr, nullptr, t);

    // GEMM3 att: 64x20, K=128
    for (int p = t; p < H2D * NATT; p += NTHREADS) wflat[p] = att_w3[p];
    __syncthreads();
    {
        int ssp = t & 63;
        int g   = t >> 6;                      // 4 groups x 5 outputs
        float acc[5];
#pragma unroll
        for (int j = 0; j < 5; j++) acc[j] = att_b3[g * 5 + j];
        for (int k = 0; k < H2D; k++) {
            float a = s.h2T[k][ssp];
#pragma unroll
            for (int j = 0; j < 5; j++)
                acc[j] = fmaf(a, wflat[k * NATT + g * 5 + j], acc[j]);
        }
#pragma unroll
        for (int j = 0; j < 5; j++) s.logits[ssp][g * 5 + j] = acc[j];
    }
    __syncthreads();

    // att softmax + store : 4 threads per sample (same warp nibble)
    {
        int ss = t >> 2, q = t & 3;
        int i = base + ss;
        float l[5];
        float mx = -1e30f;
#pragma unroll
        for (int j = 0; j < 5; j++) {
            l[j] = s.logits[ss][q * 5 + j];
            mx = fmaxf(mx, l[j]);
        }
        mx = fmaxf(mx, __shfl_xor_sync(0xffffffffu, mx, 1));
        mx = fmaxf(mx, __shfl_xor_sync(0xffffffffu, mx, 2));
        float sum = 0.f;
#pragma unroll
        for (int j = 0; j < 5; j++) { l[j] = expf(l[j] - mx); sum += l[j]; }
        sum += __shfl_xor_sync(0xffffffffu, sum, 1);
        sum += __shfl_xor_sync(0xffffffffu, sum, 2);
        float inv = 1.0f / sum;
        float* od = out + (size_t)BTOT + (size_t)i * NATT;
#pragma unroll
        for (int j = 0; j < 5; j++) od[q * 5 + j] = l[j] * inv;
    }
    __syncthreads();

    // ============================ AMT branch ================================
    for (int p = t; p < H1D; p += NTHREADS) {
        s.bbuf[p]       = amt_b1[p];
        s.bbuf[256 + p] = amt_w1[(size_t)FEATD * H1D + p];  // row 336 (masked_value)
    }
    gemm_block<FEATD, H1D, MT>(&s.featT[0][0], &s.h1T[0][0], HSTR,
                               amt_w1, s, s.bbuf, s.mv, s.bbuf + 256, t);

    for (int p = t; p < H2D; p += NTHREADS) s.bbuf[p] = amt_b2[p];
    gemm_block<H1D, H2D, HSTR>(&s.h1T[0][0], &s.h2T[0][0], HSTR,
                               amt_w2, s, s.bbuf, nullptr, nullptr, t);

    // GEMM3 amt: 64x30, K=128
    for (int p = t; p < H2D * NAMT; p += NTHREADS) wflat[p] = amt_w3[p];
    __syncthreads();
    {
        int ssp = t & 63;
        int g   = t >> 6;                      // groups of 8 (last has 6)
        int n0  = g * 8;
        float acc[8];
#pragma unroll
        for (int j = 0; j < 8; j++)
            acc[j] = (n0 + j < NAMT) ? amt_b3[n0 + j] : 0.f;
        for (int k = 0; k < H2D; k++) {
            float a = s.h2T[k][ssp];
#pragma unroll
            for (int j = 0; j < 8; j++)
                if (n0 + j < NAMT)
                    acc[j] = fmaf(a, wflat[k * NAMT + n0 + j], acc[j]);
        }
#pragma unroll
        for (int j = 0; j < 8; j++)
            if (n0 + j < NAMT) s.logits[ssp][n0 + j] = acc[j];
    }
    __syncthreads();

    // --- amt softmax -> mask -> softmax -> gumbel argmax : 4 thr/sample -----
    {
        int ss = t >> 2, q = t & 3;
        int i = base + ss;
        int nbase = q * 8;                     // q=3 covers 24..29 (6 valid)
        float l[8];
        float mx = -1e30f;
#pragma unroll
        for (int j = 0; j < 8; j++) {
            int n = nbase + j;
            l[j] = (n < NAMT) ? s.logits[ss][n] : -1e30f;
            mx = fmaxf(mx, l[j]);
        }
        mx = fmaxf(mx, __shfl_xor_sync(0xffffffffu, mx, 1));
        mx = fmaxf(mx, __shfl_xor_sync(0xffffffffu, mx, 2));
        float sum = 0.f;
#pragma unroll
        for (int j = 0; j < 8; j++) {
            int n = nbase + j;
            float e = (n < NAMT) ? expf(l[j] - mx) : 0.f;
            l[j] = e;
            sum += e;
        }
        sum += __shfl_xor_sync(0xffffffffu, sum, 1);
        sum += __shfl_xor_sync(0xffffffffu, sum, 2);
        float inv = 1.0f / sum;
#pragma unroll
        for (int j = 0; j < 8; j++) l[j] *= inv;     // amt_probs

        // bucket threshold: clamp(ceil((mv/0.1)/2), 1, 30)
        float mvv = s.mv[ss];
        float a1 = mvv / 0.1f;
        a1 = a1 / 2.0f;
        float cf = ceilf(a1);
        cf = fminf(fmaxf(cf, 1.0f), 30.0f);
        int temp = (int)cf;

        // second (masked) softmax over first `temp` buckets
        float mx2 = -1e30f;
#pragma unroll
        for (int j = 0; j < 8; j++)
            if (nbase + j < temp) mx2 = fmaxf(mx2, l[j]);
        mx2 = fmaxf(mx2, __shfl_xor_sync(0xffffffffu, mx2, 1));
        mx2 = fmaxf(mx2, __shfl_xor_sync(0xffffffffu, mx2, 2));
        float sum2 = 0.f;
#pragma unroll
        for (int j = 0; j < 8; j++) {
            float e = (nbase + j < temp) ? expf(l[j] - mx2) : 0.f;
            l[j] = e;
            sum2 += e;
        }
        sum2 += __shfl_xor_sync(0xffffffffu, sum2, 1);
        sum2 += __shfl_xor_sync(0xffffffffu, sum2, 2);
        float inv2 = 1.0f / sum2;

        float* od = out + (size_t)BTOT * (1 + NATT) + (size_t)i * NAMT;
        int best = NAMT;                       // sentinel > any valid idx
        float bestsc = -1e30f;
        unsigned gbase = (unsigned)i * (unsigned)NAMT;
#pragma unroll
        for (int j = 0; j < 8; j++) {
            int n = nbase + j;
            if (n < NAMT) {
                float a = l[j] * inv2;         // exact 0 for masked buckets
                od[n] = a;
                float sc = logf(a + 1e-20f) + gumbel_at(gbase + n);
                if (sc > bestsc) { bestsc = sc; best = n; }
            }
        }
        // nibble argmax reduce; first-index wins on exact ties
#pragma unroll
        for (int off = 1; off < 4; off <<= 1) {
            float osc = __shfl_xor_sync(0xffffffffu, bestsc, off);
            int   obn = __shfl_xor_sync(0xffffffffu, best, off);
            if (osc > bestsc || (osc == bestsc && obn < best)) {
                bestsc = osc; best = obn;
            }
        }
        if (q == 0) out[i] = (float)best;      // cnt
    }
}

extern "C" void kernel_launch(void* const* d_in, const int* in_sizes, int n_in,
                              void* d_out, int out_size) {
    const float* x  = (const float*)d_in[0];
    const int*   ei = (const int*)d_in[1];      // int32 (jax x64 disabled)
    const float* aa = (const float*)d_in[2];
    const int*   ra = (const int*)d_in[3];      // int32
    const float *aw1 = (const float*)d_in[4],  *ab1 = (const float*)d_in[5];
    const float *aw2 = (const float*)d_in[6],  *ab2 = (const float*)d_in[7];
    const float *aw3 = (const float*)d_in[8],  *ab3 = (const float*)d_in[9];
    const float *mw1 = (const float*)d_in[10], *mb1 = (const float*)d_in[11];
    const float *mw2 = (const float*)d_in[12], *mb2 = (const float*)d_in[13];
    const float *mw3 = (const float*)d_in[14], *mb3 = (const float*)d_in[15];
    float* out = (float*)d_out;

    cudaFuncSetAttribute(att_amt_policy_kernel,
                         cudaFuncAttributeMaxDynamicSharedMemorySize,
                         (int)sizeof(SM));
    const int* edge_col = ei + (long long)BTOT * NBR;  // edge_index[1]
    att_amt_policy_kernel<<<BTOT / MT, NTHREADS, sizeof(SM)>>>(
        x, edge_col, aa, ra,
        aw1, ab1, aw2, ab2, aw3, ab3,
        mw1, mb1, mw2, mb2, mw3, mb3,
        out);
}